// round 16
// baseline (speedup 1.0000x reference)
#include <cuda_runtime.h>
#include <cstdint>

// Problem constants:
// B=32, N=32, P0=16, P1=32, P2=16, R=3, D=8, V=2
// num_in = 112, RD = 24
// out per b: 16 (null) + 1024 (unary) + 32*31*16 (binary) = 16912
// This kernel: grid (3 rules, 32 b) x 1024 threads; block = one rule, all pairs.

#define NUMIN 112

typedef unsigned long long u64;

// -------- packed f32x2 helpers (Blackwell) --------
__device__ __forceinline__ u64 pk2(float a, float b) {
    u64 r; asm("mov.b64 %0, {%1,%2};" : "=l"(r) : "f"(a), "f"(b)); return r;
}
__device__ __forceinline__ void upk2(u64 v, float& a, float& b) {
    asm("mov.b64 {%0,%1}, %2;" : "=f"(a), "=f"(b) : "l"(v));
}
__device__ __forceinline__ u64 fma2(u64 a, u64 b, u64 c) {
    u64 d; asm("fma.rn.f32x2 %0, %1, %2, %3;" : "=l"(d) : "l"(a), "l"(b), "l"(c)); return d;
}
__device__ __forceinline__ u64 mul2(u64 a, u64 b) {
    u64 d; asm("mul.rn.f32x2 %0, %1, %2;" : "=l"(d) : "l"(a), "l"(b)); return d;
}
__device__ __forceinline__ void lds_wc(u64& w, u64& c, uint32_t addr) {
    asm volatile("ld.shared.v2.u64 {%0,%1}, [%2];" : "=l"(w), "=l"(c) : "r"(addr));
}
__device__ __forceinline__ uint32_t smem_u32(const void* p) {
    uint32_t a;
    asm("{ .reg .u64 t; cvta.to.shared.u64 t, %1; cvt.u32.u64 %0, t; }" : "=r"(a) : "l"(p));
    return a;
}

// ============================================================================
// Fused per-rule kernel. grid = (3 r, 32 b), block = 1024 (i = t>>5, jj = lane).
// Block (r,b): softmax for its 8 rds only; U2/PU1 for its rds; main loop over
// 32 kk x 4 rdp; writes the outputs its rule owns. No cross-block sync at all.
// ============================================================================
__global__ __launch_bounds__(1024, 1)
void kRule(const float* __restrict__ nul, const float* __restrict__ una,
           const float* __restrict__ binp, const float* __restrict__ andk,
           const float* __restrict__ ork, float* __restrict__ out) {
    __shared__ float2 sWC[8 * NUMIN];    // (w,c) for local rds lr=0..7
    __shared__ float  sU[32 * 33];       // unary transposed [k][i], stride 33
    __shared__ float4 sBW[32 * 4];       // packed binary weights [kk][q]
    __shared__ float  sU2[32 * 9];       // U2[j][lr], stride 9
    __shared__ float  sPU1[32 * 8];      // PU1[i][lr]
    __shared__ float  sN[16];
    __shared__ float  sOK[8];
    __shared__ float  sW0[32];           // per-warp nullary partials (r==0)

    const int r  = blockIdx.x;           // rule 0..2
    const int b  = blockIdx.y;           // 0..31
    const int t  = threadIdx.x;          // 0..1023
    const int i  = t >> 5;
    const int lane = t & 31;

    const int  jj     = lane;
    const bool active = (jj < 31);
    const int  jj_s   = active ? jj : 0;
    const int  j      = jj_s + (jj_s >= i);   // second object
    const int  ip     = i - (jj_s < i);       // column of (j,i) row

    // ---- hoisted xs loads (overlap phase-1 latency) ----
    float xs1[16], xs2[16];
    {
        const float4* p1 = (const float4*)(binp + (((size_t)b * 32 + i) * 31 + jj_s) * 16);
        const float4* p2 = (const float4*)(binp + (((size_t)b * 32 + j) * 31 + ip)  * 16);
        float4 va[4], vb[4];
#pragma unroll
        for (int q = 0; q < 4; q++) va[q] = p1[q];
#pragma unroll
        for (int q = 0; q < 4; q++) vb[q] = p2[q];
#pragma unroll
        for (int q = 0; q < 4; q++) {
            xs1[4 * q + 0] = va[q].x; xs1[4 * q + 1] = va[q].y;
            xs1[4 * q + 2] = va[q].z; xs1[4 * q + 3] = va[q].w;
            xs2[4 * q + 0] = vb[q].x; xs2[4 * q + 1] = vb[q].y;
            xs2[4 * q + 2] = vb[q].z; xs2[4 * q + 3] = vb[q].w;
        }
    }
    const float uk = (r == 1) ? una[(size_t)b * 1024 + i * 32 + lane] : 0.0f;

    // ---- phase 1: local softmax (896 triples), staging ----
    if (t < 896) {
        int lr = t / NUMIN, k = t - lr * NUMIN;
        const float* p = andk + ((size_t)((r * 8 + lr) * NUMIN + k)) * 3;
        float a0 = __ldg(p), a1 = __ldg(p + 1), a2 = __ldg(p + 2);
        // 2-exp softmax: divide by e2
        float r0 = __expf(a0 - a2), r1 = __expf(a1 - a2);
        float inv = __fdividef(1.0f, r0 + r1 + 1.0f);
        sWC[lr * NUMIN + k] = make_float2((r0 - r1) * inv, (r1 + 1.0f) * inv);
    } else if (t < 912) {
        sN[t - 896] = nul[b * 16 + (t - 896)];
    } else if (t < 920) {
        float x = ork[r * 8 + (t - 912)];
        sOK[t - 912] = __fdividef(1.0f, 1.0f + __expf(-x));
    }
    {
        int ii = t >> 5, k = t & 31;
        sU[k * 33 + ii] = una[b * 1024 + t];
    }
    __syncthreads();   // bar1

    // ---- phase 2: U2 (256), PU1 (256), sBW (128) ----
    if (t < 256) {
        int jx = t & 31, lr = t >> 5;
        const float2* wc = sWC + lr * NUMIN + 48;
        float pa = 1.0f, pb = 1.0f, pc = 1.0f, pd = 1.0f;
#pragma unroll
        for (int k = 0; k < 8; k++) {
            float2 w0 = wc[k],      w1 = wc[8 + k];
            float2 w2 = wc[16 + k], w3 = wc[24 + k];
            pa *= fmaf(sU[k * 33 + jx],        w0.x, w0.y);
            pb *= fmaf(sU[(8 + k) * 33 + jx],  w1.x, w1.y);
            pc *= fmaf(sU[(16 + k) * 33 + jx], w2.x, w2.y);
            pd *= fmaf(sU[(24 + k) * 33 + jx], w3.x, w3.y);
        }
        sU2[jx * 9 + lr] = (pa * pb) * (pc * pd);
    } else if (t < 512) {
        int tid = t - 256;
        int ii = tid & 31, lr = tid >> 5;
        const float2* wc = sWC + lr * NUMIN;
        float pa = 1.0f, pb = 1.0f, pc = 1.0f, pd = 1.0f;
#pragma unroll
        for (int k = 0; k < 8; k++) {
            float2 w0 = wc[k], w1 = wc[8 + k];
            pa *= fmaf(sN[k],     w0.x, w0.y);
            pb *= fmaf(sN[8 + k], w1.x, w1.y);
        }
#pragma unroll
        for (int k = 0; k < 16; k++) {
            float2 w0 = wc[16 + k], w1 = wc[32 + k];
            pc *= fmaf(sU[k * 33 + ii],        w0.x, w0.y);
            pd *= fmaf(sU[(16 + k) * 33 + ii], w1.x, w1.y);
        }
        sPU1[ii * 8 + lr] = ((pa * pb) * (pc * pd)) * sOK[lr];
    } else if (t < 640) {
        int idx = t - 512;                  // 0..127
        int kk = idx >> 2, q = idx & 3;
        int slice = (kk < 16) ? (80 + kk) : (96 + kk - 16);
        float2 lo = sWC[(2 * q)     * NUMIN + slice];
        float2 hi = sWC[(2 * q + 1) * NUMIN + slice];
        sBW[kk * 4 + q] = make_float4(lo.x, hi.x, lo.y, hi.y);
    }
    __syncthreads();   // bar2

    // ---- main loop: 32 kk x 4 rdp ----
    u64 acc[4];
#pragma unroll
    for (int q = 0; q < 4; q++) {
        float lo = sPU1[i * 8 + 2 * q]     * sU2[j * 9 + 2 * q];
        float hi = sPU1[i * 8 + 2 * q + 1] * sU2[j * 9 + 2 * q + 1];
        acc[q] = pk2(lo, hi);
    }

    const uint32_t sb = smem_u32(sBW);
#pragma unroll
    for (int kk = 0; kk < 32; kk++) {
        float x = (kk < 16) ? xs1[kk] : xs2[kk - 16];
        u64 xx = pk2(x, x);
#pragma unroll
        for (int q = 0; q < 4; q++) {
            u64 w, c;
            lds_wc(w, c, sb + (uint32_t)((kk * 4 + q) * 16));
            acc[q] = mul2(acc[q], fma2(xx, w, c));
        }
    }

    // ---- per-rule disjunct product over D=8 ----
    float tv[8];
#pragma unroll
    for (int q = 0; q < 4; q++) {
        float lo, hi;
        upk2(acc[q], lo, hi);
        tv[2 * q]     = 1.0f - lo;
        tv[2 * q + 1] = 1.0f - hi;
    }
    float pr = ((tv[0] * tv[1]) * (tv[2] * tv[3])) * ((tv[4] * tv[5]) * (tv[6] * tv[7]));

    // ---- rule-specific outputs ----
    if (r == 2) {
        // binary rows: channels 0..14 copy, channel 15 merged
        if (active) {
            float4 o[4];
#pragma unroll
            for (int q = 0; q < 4; q++) {
                o[q].x = xs1[4 * q + 0]; o[q].y = xs1[4 * q + 1];
                o[q].z = xs1[4 * q + 2]; o[q].w = xs1[4 * q + 3];
            }
            o[3].w = 1.0f - (1.0f - xs1[15]) * pr;
            float4* ob = (float4*)(out + (size_t)b * 16912 + 1040 + (size_t)(i * 31 + jj) * 16);
#pragma unroll
            for (int q = 0; q < 4; q++) ob[q] = o[q];
        }
    } else if (r == 1) {
        // unary rows: reduce pr over jj within the warp
        float rp = active ? pr : 1.0f;
#pragma unroll
        for (int s = 16; s > 0; s >>= 1)
            rp *= __shfl_xor_sync(0xFFFFFFFFu, rp, s);
        float uv = (lane < 31) ? uk : (1.0f - (1.0f - uk) * rp);
        out[(size_t)b * 16912 + 16 + i * 32 + lane] = uv;
    } else {
        // nullary: full in-block product over (i, jj)
        float rp = active ? pr : 1.0f;
#pragma unroll
        for (int s = 16; s > 0; s >>= 1)
            rp *= __shfl_xor_sync(0xFFFFFFFFu, rp, s);
        if (lane == 0) sW0[i] = rp;
        __syncthreads();
        if (t < 15) {
            out[(size_t)b * 16912 + t] = sN[t];
        }
        if (t < 32 && t >= 0 && (t >> 5) == 0) {
            // warp 0: product of 32 warp partials
            float p = sW0[lane];
#pragma unroll
            for (int s = 16; s > 0; s >>= 1)
                p *= __shfl_xor_sync(0xFFFFFFFFu, p, s);
            if (lane == 0)
                out[(size_t)b * 16912 + 15] = 1.0f - (1.0f - sN[15]) * p;
        }
    }
}

// ============================================================================
extern "C" void kernel_launch(void* const* d_in, const int* in_sizes, int n_in,
                              void* d_out, int out_size) {
    // Identify the 5 inputs by rank order of element count (all distinct):
    //   ork (24) < nul (512) < andk (8064) < una (32768) < binp (507904)
    int order[5] = {0, 1, 2, 3, 4};
    for (int a = 1; a < 5 && a < n_in; a++) {
        int key = order[a];
        int ks = in_sizes[key];
        int bpos = a - 1;
        while (bpos >= 0 && in_sizes[order[bpos]] > ks) {
            order[bpos + 1] = order[bpos];
            bpos--;
        }
        order[bpos + 1] = key;
    }
    const float* ork  = (const float*)d_in[order[0]];
    const float* nul  = (const float*)d_in[order[1]];
    const float* andk = (const float*)d_in[order[2]];
    const float* una  = (const float*)d_in[order[3]];
    const float* binp = (const float*)d_in[order[4]];
    float* out = (float*)d_out;

    kRule<<<dim3(3, 32), 1024>>>(nul, una, binp, andk, ork, out);
}

// round 17
// speedup vs baseline: 1.0043x; 1.0043x over previous
#include <cuda_runtime.h>
#include <cstdint>

// Problem constants:
// B=32, N=32, P0=16, P1=32, P2=16, R=3, D=8, V=2
// num_in = 112, RD = 24
// out per b: 16 (null) + 1024 (unary) + 32*31*16 (binary) = 16912
// This kernel: grid (3 rules, 32 b) x 1024 threads; block = one rule, all pairs.

#define NUMIN 112

typedef unsigned long long u64;

// -------- packed f32x2 helpers (Blackwell) --------
__device__ __forceinline__ u64 pk2(float a, float b) {
    u64 r; asm("mov.b64 %0, {%1,%2};" : "=l"(r) : "f"(a), "f"(b)); return r;
}
__device__ __forceinline__ void upk2(u64 v, float& a, float& b) {
    asm("mov.b64 {%0,%1}, %2;" : "=f"(a), "=f"(b) : "l"(v));
}
__device__ __forceinline__ u64 fma2(u64 a, u64 b, u64 c) {
    u64 d; asm("fma.rn.f32x2 %0, %1, %2, %3;" : "=l"(d) : "l"(a), "l"(b), "l"(c)); return d;
}
__device__ __forceinline__ u64 mul2(u64 a, u64 b) {
    u64 d; asm("mul.rn.f32x2 %0, %1, %2;" : "=l"(d) : "l"(a), "l"(b)); return d;
}
__device__ __forceinline__ void lds_wc(u64& w, u64& c, uint32_t addr) {
    asm volatile("ld.shared.v2.u64 {%0,%1}, [%2];" : "=l"(w), "=l"(c) : "r"(addr));
}
__device__ __forceinline__ uint32_t smem_u32(const void* p) {
    uint32_t a;
    asm("{ .reg .u64 t; cvta.to.shared.u64 t, %1; cvt.u32.u64 %0, t; }" : "=r"(a) : "l"(p));
    return a;
}

// ============================================================================
// Fused per-rule kernel. grid = (3 r, 32 b), block = 1024 (i = t>>5, jj = lane).
// Block (r,b): softmax for its 8 rds only; U2/PU1 for its rds; main loop over
// 32 kk x 4 rdp; writes the outputs its rule owns. No cross-block sync at all.
// ============================================================================
__global__ __launch_bounds__(1024, 1)
void kRule(const float* __restrict__ nul, const float* __restrict__ una,
           const float* __restrict__ binp, const float* __restrict__ andk,
           const float* __restrict__ ork, float* __restrict__ out) {
    __shared__ float2 sWC[8 * NUMIN];    // (w,c) for local rds lr=0..7
    __shared__ float  sU[32 * 33];       // unary transposed [k][i], stride 33
    __shared__ float4 sBW[32 * 4];       // packed binary weights [kk][q]
    __shared__ float  sU2[32 * 9];       // U2[j][lr], stride 9
    __shared__ float  sPU1[32 * 8];      // PU1[i][lr]
    __shared__ float  sN[16];
    __shared__ float  sOK[8];
    __shared__ float  sW0[32];           // per-warp nullary partials (r==0)

    const int r  = blockIdx.x;           // rule 0..2
    const int b  = blockIdx.y;           // 0..31
    const int t  = threadIdx.x;          // 0..1023
    const int i  = t >> 5;
    const int lane = t & 31;

    const int  jj     = lane;
    const bool active = (jj < 31);
    const int  jj_s   = active ? jj : 0;
    const int  j      = jj_s + (jj_s >= i);   // second object
    const int  ip     = i - (jj_s < i);       // column of (j,i) row

    // ---- hoisted xs loads (overlap phase-1 latency) ----
    float xs1[16], xs2[16];
    {
        const float4* p1 = (const float4*)(binp + (((size_t)b * 32 + i) * 31 + jj_s) * 16);
        const float4* p2 = (const float4*)(binp + (((size_t)b * 32 + j) * 31 + ip)  * 16);
        float4 va[4], vb[4];
#pragma unroll
        for (int q = 0; q < 4; q++) va[q] = p1[q];
#pragma unroll
        for (int q = 0; q < 4; q++) vb[q] = p2[q];
#pragma unroll
        for (int q = 0; q < 4; q++) {
            xs1[4 * q + 0] = va[q].x; xs1[4 * q + 1] = va[q].y;
            xs1[4 * q + 2] = va[q].z; xs1[4 * q + 3] = va[q].w;
            xs2[4 * q + 0] = vb[q].x; xs2[4 * q + 1] = vb[q].y;
            xs2[4 * q + 2] = vb[q].z; xs2[4 * q + 3] = vb[q].w;
        }
    }
    const float uk = (r == 1) ? una[(size_t)b * 1024 + i * 32 + lane] : 0.0f;

    // ---- phase 1: local softmax (896 triples), staging ----
    if (t < 896) {
        int lr = t / NUMIN, k = t - lr * NUMIN;
        const float* p = andk + ((size_t)((r * 8 + lr) * NUMIN + k)) * 3;
        float a0 = __ldg(p), a1 = __ldg(p + 1), a2 = __ldg(p + 2);
        // 2-exp softmax: divide by e2
        float r0 = __expf(a0 - a2), r1 = __expf(a1 - a2);
        float inv = __fdividef(1.0f, r0 + r1 + 1.0f);
        sWC[lr * NUMIN + k] = make_float2((r0 - r1) * inv, (r1 + 1.0f) * inv);
    } else if (t < 912) {
        sN[t - 896] = nul[b * 16 + (t - 896)];
    } else if (t < 920) {
        float x = ork[r * 8 + (t - 912)];
        sOK[t - 912] = __fdividef(1.0f, 1.0f + __expf(-x));
    }
    {
        int ii = t >> 5, k = t & 31;
        sU[k * 33 + ii] = una[b * 1024 + t];
    }
    __syncthreads();   // bar1

    // ---- phase 2: U2 (256), PU1 (256), sBW (128) ----
    if (t < 256) {
        int jx = t & 31, lr = t >> 5;
        const float2* wc = sWC + lr * NUMIN + 48;
        float pa = 1.0f, pb = 1.0f, pc = 1.0f, pd = 1.0f;
#pragma unroll
        for (int k = 0; k < 8; k++) {
            float2 w0 = wc[k],      w1 = wc[8 + k];
            float2 w2 = wc[16 + k], w3 = wc[24 + k];
            pa *= fmaf(sU[k * 33 + jx],        w0.x, w0.y);
            pb *= fmaf(sU[(8 + k) * 33 + jx],  w1.x, w1.y);
            pc *= fmaf(sU[(16 + k) * 33 + jx], w2.x, w2.y);
            pd *= fmaf(sU[(24 + k) * 33 + jx], w3.x, w3.y);
        }
        sU2[jx * 9 + lr] = (pa * pb) * (pc * pd);
    } else if (t < 512) {
        int tid = t - 256;
        int ii = tid & 31, lr = tid >> 5;
        const float2* wc = sWC + lr * NUMIN;
        float pa = 1.0f, pb = 1.0f, pc = 1.0f, pd = 1.0f;
#pragma unroll
        for (int k = 0; k < 8; k++) {
            float2 w0 = wc[k], w1 = wc[8 + k];
            pa *= fmaf(sN[k],     w0.x, w0.y);
            pb *= fmaf(sN[8 + k], w1.x, w1.y);
        }
#pragma unroll
        for (int k = 0; k < 16; k++) {
            float2 w0 = wc[16 + k], w1 = wc[32 + k];
            pc *= fmaf(sU[k * 33 + ii],        w0.x, w0.y);
            pd *= fmaf(sU[(16 + k) * 33 + ii], w1.x, w1.y);
        }
        sPU1[ii * 8 + lr] = ((pa * pb) * (pc * pd)) * sOK[lr];
    } else if (t < 640) {
        int idx = t - 512;                  // 0..127
        int kk = idx >> 2, q = idx & 3;
        int slice = (kk < 16) ? (80 + kk) : (96 + kk - 16);
        float2 lo = sWC[(2 * q)     * NUMIN + slice];
        float2 hi = sWC[(2 * q + 1) * NUMIN + slice];
        sBW[kk * 4 + q] = make_float4(lo.x, hi.x, lo.y, hi.y);
    }
    __syncthreads();   // bar2

    // ---- main loop: 32 kk x 4 rdp ----
    u64 acc[4];
#pragma unroll
    for (int q = 0; q < 4; q++) {
        float lo = sPU1[i * 8 + 2 * q]     * sU2[j * 9 + 2 * q];
        float hi = sPU1[i * 8 + 2 * q + 1] * sU2[j * 9 + 2 * q + 1];
        acc[q] = pk2(lo, hi);
    }

    const uint32_t sb = smem_u32(sBW);
#pragma unroll
    for (int kk = 0; kk < 32; kk++) {
        float x = (kk < 16) ? xs1[kk] : xs2[kk - 16];
        u64 xx = pk2(x, x);
#pragma unroll
        for (int q = 0; q < 4; q++) {
            u64 w, c;
            lds_wc(w, c, sb + (uint32_t)((kk * 4 + q) * 16));
            acc[q] = mul2(acc[q], fma2(xx, w, c));
        }
    }

    // ---- per-rule disjunct product over D=8 ----
    float tv[8];
#pragma unroll
    for (int q = 0; q < 4; q++) {
        float lo, hi;
        upk2(acc[q], lo, hi);
        tv[2 * q]     = 1.0f - lo;
        tv[2 * q + 1] = 1.0f - hi;
    }
    float pr = ((tv[0] * tv[1]) * (tv[2] * tv[3])) * ((tv[4] * tv[5]) * (tv[6] * tv[7]));

    // ---- rule-specific outputs ----
    if (r == 2) {
        // binary rows: channels 0..14 copy, channel 15 merged
        if (active) {
            float4 o[4];
#pragma unroll
            for (int q = 0; q < 4; q++) {
                o[q].x = xs1[4 * q + 0]; o[q].y = xs1[4 * q + 1];
                o[q].z = xs1[4 * q + 2]; o[q].w = xs1[4 * q + 3];
            }
            o[3].w = 1.0f - (1.0f - xs1[15]) * pr;
            float4* ob = (float4*)(out + (size_t)b * 16912 + 1040 + (size_t)(i * 31 + jj) * 16);
#pragma unroll
            for (int q = 0; q < 4; q++) ob[q] = o[q];
        }
    } else if (r == 1) {
        // unary rows: reduce pr over jj within the warp
        float rp = active ? pr : 1.0f;
#pragma unroll
        for (int s = 16; s > 0; s >>= 1)
            rp *= __shfl_xor_sync(0xFFFFFFFFu, rp, s);
        float uv = (lane < 31) ? uk : (1.0f - (1.0f - uk) * rp);
        out[(size_t)b * 16912 + 16 + i * 32 + lane] = uv;
    } else {
        // nullary: full in-block product over (i, jj)
        float rp = active ? pr : 1.0f;
#pragma unroll
        for (int s = 16; s > 0; s >>= 1)
            rp *= __shfl_xor_sync(0xFFFFFFFFu, rp, s);
        if (lane == 0) sW0[i] = rp;
        __syncthreads();
        if (t < 15) {
            out[(size_t)b * 16912 + t] = sN[t];
        }
        if (t < 32 && t >= 0 && (t >> 5) == 0) {
            // warp 0: product of 32 warp partials
            float p = sW0[lane];
#pragma unroll
            for (int s = 16; s > 0; s >>= 1)
                p *= __shfl_xor_sync(0xFFFFFFFFu, p, s);
            if (lane == 0)
                out[(size_t)b * 16912 + 15] = 1.0f - (1.0f - sN[15]) * p;
        }
    }
}

// ============================================================================
extern "C" void kernel_launch(void* const* d_in, const int* in_sizes, int n_in,
                              void* d_out, int out_size) {
    // Identify the 5 inputs by rank order of element count (all distinct):
    //   ork (24) < nul (512) < andk (8064) < una (32768) < binp (507904)
    int order[5] = {0, 1, 2, 3, 4};
    for (int a = 1; a < 5 && a < n_in; a++) {
        int key = order[a];
        int ks = in_sizes[key];
        int bpos = a - 1;
        while (bpos >= 0 && in_sizes[order[bpos]] > ks) {
            order[bpos + 1] = order[bpos];
            bpos--;
        }
        order[bpos + 1] = key;
    }
    const float* ork  = (const float*)d_in[order[0]];
    const float* nul  = (const float*)d_in[order[1]];
    const float* andk = (const float*)d_in[order[2]];
    const float* una  = (const float*)d_in[order[3]];
    const float* binp = (const float*)d_in[order[4]];
    float* out = (float*)d_out;

    kRule<<<dim3(3, 32), 1024>>>(nul, una, binp, andk, ork, out);
}